// round 13
// baseline (speedup 1.0000x reference)
#include <cuda_runtime.h>
#include <math.h>

#define NCLS 1000
#define NV4  250    // 1000 floats = 250 float4 per row
#define RPB  8      // rows per block

// Monotone float -> u32 map (order-preserving; 0 is the bottom identity)
__device__ __forceinline__ unsigned fmap(float x) {
    int i = __float_as_int(x);
    return (i < 0) ? ~(unsigned)i : ((unsigned)i | 0x80000000u);
}
__device__ __forceinline__ float funmap(unsigned u) {
    int i = (u & 0x80000000u) ? (int)(u & 0x7FFFFFFFu) : ~(int)u;
    return __int_as_float(i);
}

// Self-resetting cross-launch scratch (zero at load; last block re-zeros)
__device__ unsigned g_gmax  = 0;
__device__ unsigned g_count = 0;

__global__ __launch_bounds__(256, 5) void margin_kernel(
    const float* __restrict__ o1, const float* __restrict__ o2,
    const float* __restrict__ o3, const float* __restrict__ o4,
    const float* __restrict__ mim, const int* __restrict__ targets,
    float* __restrict__ out_max, float* __restrict__ out_thr)
{
    const int tid  = threadIdx.x;
    const int warp = tid >> 5, lane = tid & 31;
    const bool active = (tid < NV4);
    const int row0 = blockIdx.x * RPB;

    const float* mats[5] = {o1, o2, o3, o4, mim};

    __shared__ float    buf[2][5][NCLS];   // 40 KB double buffer
    __shared__ float    s_tgt[2][5];
    __shared__ unsigned s_red[2][5][8];

    // per-thread cp.async issue of one row-group into parity buffer p
    auto issue = [&](int row, int p) {
        if (active) {
            const size_t goff = (size_t)row * NCLS + tid * 4;
            #pragma unroll
            for (int m = 0; m < 5; m++) {
                unsigned saddr = (unsigned)__cvta_generic_to_shared(&buf[p][m][tid * 4]);
                asm volatile("cp.async.cg.shared.global [%0], [%1], 16;\n"
                             :: "r"(saddr), "l"(mats[m] + goff) : "memory");
            }
        }
        asm volatile("cp.async.commit_group;\n" ::: "memory");
    };

    float gblk = -INFINITY;

    issue(row0, 0);                              // prologue

    #pragma unroll 1
    for (int r = 0; r < RPB; r++) {
        const int row = row0 + r;
        const int par = r & 1;

        if (r + 1 < RPB) {
            issue(row0 + r + 1, (r + 1) & 1);    // keep next row in flight
            asm volatile("cp.async.wait_group 1;\n" ::: "memory");
        } else {
            asm volatile("cp.async.wait_group 0;\n" ::: "memory");
        }

        const int t = targets[row];
        const int town = t >> 2, tsub = t & 3;
        const bool own = (tid == town);

        // ---- per-thread max (own smem slice only; no barrier needed) ----
        unsigned u[5];
        #pragma unroll
        for (int m = 0; m < 5; m++) {
            float a = -INFINITY, b = -INFINITY, c = -INFINITY, d = -INFINITY;
            if (active) {
                float4 v = *reinterpret_cast<const float4*>(&buf[par][m][tid * 4]);
                a = v.x; b = v.y; c = v.z; d = v.w;
            }
            float mx = fmaxf(fmaxf(a, b), fmaxf(c, d));
            if (own) {                           // capture target, exclude it
                float tv = (tsub == 0) ? a : (tsub == 1) ? b : (tsub == 2) ? c : d;
                s_tgt[par][m] = tv;
                float ea = (tsub == 0) ? -INFINITY : a;
                float eb = (tsub == 1) ? -INFINITY : b;
                float ec = (tsub == 2) ? -INFINITY : c;
                float ed = (tsub == 3) ? -INFINITY : d;
                mx = fmaxf(fmaxf(ea, eb), fmaxf(ec, ed));
            }
            u[m] = fmap(mx);
        }

        // ---- warp reduction: single REDUX per matrix ----
        #pragma unroll
        for (int m = 0; m < 5; m++)
            u[m] = __reduce_max_sync(0xFFFFFFFFu, u[m]);

        if (lane == 0) {
            #pragma unroll
            for (int m = 0; m < 5; m++) s_red[par][m][warp] = u[m];
        }
        __syncthreads();     // one barrier per row (parity-double-buffered s_red)

        // ---- epilogue (thread 0); other warps roll into next row ----
        if (tid == 0) {
            float m_excl[5];
            #pragma unroll
            for (int m = 0; m < 5; m++) {
                unsigned um = s_red[par][m][0];
                #pragma unroll
                for (int w = 1; w < 8; w++) um = max(um, s_red[par][m][w]);
                m_excl[m] = funmap(um);
            }

            float g = -INFINITY;
            #pragma unroll
            for (int m = 0; m < 4; m++) g = fmaxf(g, fmaxf(m_excl[m], s_tgt[par][m]));
            gblk = fmaxf(gblk, g);

            float margin[5];
            #pragma unroll
            for (int m = 0; m < 5; m++)
                margin[m] = fmaxf(0.0f, (s_tgt[par][m] - m_excl[m]) * 0.5f);

            float mx = margin[0];
            #pragma unroll
            for (int m = 1; m < 5; m++) mx = fmaxf(mx, margin[m]);
            float e[5], s = 0.0f;
            #pragma unroll
            for (int m = 0; m < 5; m++) { e[m] = __expf(margin[m] - mx); s += e[m]; }
            float inv = 1.0f / s;
            float* dst = out_thr + (size_t)row * 5;
            #pragma unroll
            for (int m = 0; m < 5; m++) dst[m] = e[m] * inv;
        }
    }

    // ---- one atomic pair per block; last block publishes + resets ----
    if (tid == 0) {
        atomicMax(&g_gmax, fmap(gblk));
        __threadfence();
        unsigned c = atomicAdd(&g_count, 1);
        if (c == gridDim.x - 1) {
            unsigned final_u = atomicMax(&g_gmax, 0u);
            *out_max = funmap(final_u);
            atomicExch(&g_gmax, 0u);
            atomicExch(&g_count, 0u);
        }
    }
}

extern "C" void kernel_launch(void* const* d_in, const int* in_sizes, int n_in,
                              void* d_out, int out_size)
{
    const float* o1  = (const float*)d_in[0];
    const float* o2  = (const float*)d_in[1];
    const float* o3  = (const float*)d_in[2];
    const float* o4  = (const float*)d_in[3];
    const float* mim = (const float*)d_in[4];
    const int*   tgt = (const int*)d_in[5];

    const int n = in_sizes[5];          // 16384 rows (divisible by RPB)
    float* out = (float*)d_out;

    float* out_thr = out + ((size_t)out_size - (size_t)n * 5);
    float* out_max = out;

    margin_kernel<<<n / RPB, 256>>>(o1, o2, o3, o4, mim, tgt, out_max, out_thr);
}

// round 14
// speedup vs baseline: 1.1988x; 1.1988x over previous
#include <cuda_runtime.h>
#include <math.h>

#define NCLS 1000
#define NV4  250   // 1000 floats = 250 float4 per row

// Monotone float -> u32 map (order-preserving; 0 is the bottom identity)
__device__ __forceinline__ unsigned fmap(float x) {
    int i = __float_as_int(x);
    return (i < 0) ? ~(unsigned)i : ((unsigned)i | 0x80000000u);
}
__device__ __forceinline__ float funmap(unsigned u) {
    int i = (u & 0x80000000u) ? (int)(u & 0x7FFFFFFFu) : ~(int)u;
    return __int_as_float(i);
}

// Self-resetting cross-launch scratch (zero at load; last block re-zeros)
__device__ unsigned g_gmax  = 0;
__device__ unsigned g_count = 0;

__global__ __launch_bounds__(128, 10) void margin_kernel(
    const float* __restrict__ o1, const float* __restrict__ o2,
    const float* __restrict__ o3, const float* __restrict__ o4,
    const float* __restrict__ mim, const int* __restrict__ targets,
    float* __restrict__ out_max, float* __restrict__ out_thr)
{
    const int row = blockIdx.x;
    const int tid = threadIdx.x;          // 0..127
    const int t   = targets[row];
    const int town   = t >> 2;            // target float4 index (0..249)
    const int tchunk = (town >= 128);     // which chunk holds it
    const int towner = tchunk ? (town - 128) : town;
    const int tsub   = t & 3;

    const float* mats[5] = {o1, o2, o3, o4, mim};

    __shared__ float    s_tgt[5];
    __shared__ unsigned s_red[5][4];

    // ---- load phase: 10 independent streaming float4 loads per thread ----
    // chunk 0: idx = tid (0..127), chunk 1: idx = 128+tid (128..249)
    const bool act1 = (tid < NV4 - 128);  // tid < 122
    float4 v0[5], v1[5];
    {
        const size_t base = (size_t)row * NCLS;
        #pragma unroll
        for (int m = 0; m < 5; m++)
            v0[m] = __ldcs(reinterpret_cast<const float4*>(mats[m] + base) + tid);
        #pragma unroll
        for (int m = 0; m < 5; m++)
            if (act1)
                v1[m] = __ldcs(reinterpret_cast<const float4*>(mats[m] + base) + 128 + tid);
    }

    // ---- per-thread max over both chunks (excluding target) + capture ----
    const bool own  = (tid == towner);
    const bool own0 = own && !tchunk;
    const bool own1 = own &&  tchunk;
    unsigned u[5];
    #pragma unroll
    for (int m = 0; m < 5; m++) {
        float a0 = v0[m].x, b0 = v0[m].y, c0 = v0[m].z, d0 = v0[m].w;
        float a1 = -INFINITY, b1 = -INFINITY, c1 = -INFINITY, d1 = -INFINITY;
        if (act1) { a1 = v1[m].x; b1 = v1[m].y; c1 = v1[m].z; d1 = v1[m].w; }
        if (own0) {
            float tv = (tsub == 0) ? a0 : (tsub == 1) ? b0 : (tsub == 2) ? c0 : d0;
            s_tgt[m] = tv;
            if (tsub == 0) a0 = -INFINITY; else if (tsub == 1) b0 = -INFINITY;
            else if (tsub == 2) c0 = -INFINITY; else d0 = -INFINITY;
        }
        if (own1) {
            float tv = (tsub == 0) ? a1 : (tsub == 1) ? b1 : (tsub == 2) ? c1 : d1;
            s_tgt[m] = tv;
            if (tsub == 0) a1 = -INFINITY; else if (tsub == 1) b1 = -INFINITY;
            else if (tsub == 2) c1 = -INFINITY; else d1 = -INFINITY;
        }
        float mx = fmaxf(fmaxf(fmaxf(a0, b0), fmaxf(c0, d0)),
                         fmaxf(fmaxf(a1, b1), fmaxf(c1, d1)));
        u[m] = fmap(mx);
    }

    // ---- warp reduction: single REDUX per matrix ----
    #pragma unroll
    for (int m = 0; m < 5; m++)
        u[m] = __reduce_max_sync(0xFFFFFFFFu, u[m]);

    const int warp = tid >> 5, lane = tid & 31;
    if (lane == 0) {
        #pragma unroll
        for (int m = 0; m < 5; m++) s_red[m][warp] = u[m];
    }
    __syncthreads();

    // ---- final combine + softmax + global-max protocol by thread 0 ----
    if (tid == 0) {
        float m_excl[5];
        #pragma unroll
        for (int m = 0; m < 5; m++) {
            unsigned um = s_red[m][0];
            #pragma unroll
            for (int w = 1; w < 4; w++) um = max(um, s_red[m][w]);
            m_excl[m] = funmap(um);
        }

        // row max over mats 0..3 (restore excluded target element)
        float g = -INFINITY;
        #pragma unroll
        for (int m = 0; m < 4; m++) g = fmaxf(g, fmaxf(m_excl[m], s_tgt[m]));

        // margin = max(0, tgt - max_excl), /TEMPERATURE(=2) folded in
        float margin[5];
        #pragma unroll
        for (int m = 0; m < 5; m++)
            margin[m] = fmaxf(0.0f, (s_tgt[m] - m_excl[m]) * 0.5f);

        float mx = margin[0];
        #pragma unroll
        for (int m = 1; m < 5; m++) mx = fmaxf(mx, margin[m]);
        float e[5], s = 0.0f;
        #pragma unroll
        for (int m = 0; m < 5; m++) { e[m] = __expf(margin[m] - mx); s += e[m]; }
        float inv = 1.0f / s;
        float* dst = out_thr + (size_t)row * 5;
        #pragma unroll
        for (int m = 0; m < 5; m++) dst[m] = e[m] * inv;

        // ---- global max: atomic accumulate, last block publishes + resets ----
        atomicMax(&g_gmax, fmap(g));
        __threadfence();
        unsigned c = atomicAdd(&g_count, 1);
        if (c == gridDim.x - 1) {
            unsigned final_u = atomicMax(&g_gmax, 0u);
            *out_max = funmap(final_u);
            atomicExch(&g_gmax, 0u);
            atomicExch(&g_count, 0u);
        }
    }
}

extern "C" void kernel_launch(void* const* d_in, const int* in_sizes, int n_in,
                              void* d_out, int out_size)
{
    const float* o1  = (const float*)d_in[0];
    const float* o2  = (const float*)d_in[1];
    const float* o3  = (const float*)d_in[2];
    const float* o4  = (const float*)d_in[3];
    const float* mim = (const float*)d_in[4];
    const int*   tgt = (const int*)d_in[5];

    const int n = in_sizes[5];          // 16384 rows
    float* out = (float*)d_out;

    float* out_thr = out + ((size_t)out_size - (size_t)n * 5);
    float* out_max = out;

    margin_kernel<<<n, 128>>>(o1, o2, o3, o4, mim, tgt, out_max, out_thr);
}

// round 15
// speedup vs baseline: 1.2418x; 1.0359x over previous
#include <cuda_runtime.h>
#include <math.h>

#define NCLS 1000
#define NV4  250   // 1000 floats = 250 float4 per row

// Monotone float -> u32 map (order-preserving; 0 is the bottom identity)
__device__ __forceinline__ unsigned fmap(float x) {
    int i = __float_as_int(x);
    return (i < 0) ? ~(unsigned)i : ((unsigned)i | 0x80000000u);
}
__device__ __forceinline__ float funmap(unsigned u) {
    int i = (u & 0x80000000u) ? (int)(u & 0x7FFFFFFFu) : ~(int)u;
    return __int_as_float(i);
}

// Self-resetting cross-launch scratch (zero at load; last block re-zeros)
__device__ unsigned g_gmax  = 0;
__device__ unsigned g_count = 0;

__global__ __launch_bounds__(128, 10) void margin_kernel(
    const float* __restrict__ o1, const float* __restrict__ o2,
    const float* __restrict__ o3, const float* __restrict__ o4,
    const float* __restrict__ mim, const int* __restrict__ targets,
    float* __restrict__ out_max, float* __restrict__ out_thr)
{
    const int row = blockIdx.x;
    const int tid = threadIdx.x;          // 0..127
    const int t   = targets[row];
    const int town   = t >> 2;            // target float4 index (0..249)
    const int tchunk = (town >= 128);     // which chunk holds it
    const int towner = tchunk ? (town - 128) : town;
    const int tsub   = t & 3;

    const float* mats[5] = {o1, o2, o3, o4, mim};

    __shared__ float    s_tgt[5];
    __shared__ unsigned s_red[5][4];

    // ---- load phase: 10 independent streaming float4 loads per thread ----
    // chunk 0: idx = tid (0..127), chunk 1: idx = 128+tid (128..249)
    const bool act1 = (tid < NV4 - 128);  // tid < 122
    float4 v0[5], v1[5];
    {
        const size_t base = (size_t)row * NCLS;
        #pragma unroll
        for (int m = 0; m < 5; m++)
            v0[m] = __ldcs(reinterpret_cast<const float4*>(mats[m] + base) + tid);
        #pragma unroll
        for (int m = 0; m < 5; m++)
            if (act1)
                v1[m] = __ldcs(reinterpret_cast<const float4*>(mats[m] + base) + 128 + tid);
    }

    // ---- per-thread max over both chunks (excluding target) + capture ----
    const bool own  = (tid == towner);
    const bool own0 = own && !tchunk;
    const bool own1 = own &&  tchunk;
    unsigned u[5];
    #pragma unroll
    for (int m = 0; m < 5; m++) {
        float a0 = v0[m].x, b0 = v0[m].y, c0 = v0[m].z, d0 = v0[m].w;
        float a1 = -INFINITY, b1 = -INFINITY, c1 = -INFINITY, d1 = -INFINITY;
        if (act1) { a1 = v1[m].x; b1 = v1[m].y; c1 = v1[m].z; d1 = v1[m].w; }
        if (own0) {
            float tv = (tsub == 0) ? a0 : (tsub == 1) ? b0 : (tsub == 2) ? c0 : d0;
            s_tgt[m] = tv;
            if (tsub == 0) a0 = -INFINITY; else if (tsub == 1) b0 = -INFINITY;
            else if (tsub == 2) c0 = -INFINITY; else d0 = -INFINITY;
        }
        if (own1) {
            float tv = (tsub == 0) ? a1 : (tsub == 1) ? b1 : (tsub == 2) ? c1 : d1;
            s_tgt[m] = tv;
            if (tsub == 0) a1 = -INFINITY; else if (tsub == 1) b1 = -INFINITY;
            else if (tsub == 2) c1 = -INFINITY; else d1 = -INFINITY;
        }
        float mx = fmaxf(fmaxf(fmaxf(a0, b0), fmaxf(c0, d0)),
                         fmaxf(fmaxf(a1, b1), fmaxf(c1, d1)));
        u[m] = fmap(mx);
    }

    // ---- warp reduction: single REDUX per matrix ----
    #pragma unroll
    for (int m = 0; m < 5; m++)
        u[m] = __reduce_max_sync(0xFFFFFFFFu, u[m]);

    const int warp = tid >> 5, lane = tid & 31;
    if (lane == 0) {
        #pragma unroll
        for (int m = 0; m < 5; m++) s_red[m][warp] = u[m];
    }
    __syncthreads();

    // ---- final combine + softmax + global-max protocol by thread 0 ----
    if (tid == 0) {
        float m_excl[5];
        #pragma unroll
        for (int m = 0; m < 5; m++) {
            unsigned um = s_red[m][0];
            #pragma unroll
            for (int w = 1; w < 4; w++) um = max(um, s_red[m][w]);
            m_excl[m] = funmap(um);
        }

        // row max over mats 0..3 (restore excluded target element)
        float g = -INFINITY;
        #pragma unroll
        for (int m = 0; m < 4; m++) g = fmaxf(g, fmaxf(m_excl[m], s_tgt[m]));

        // margin = max(0, tgt - max_excl), /TEMPERATURE(=2) folded in
        float margin[5];
        #pragma unroll
        for (int m = 0; m < 5; m++)
            margin[m] = fmaxf(0.0f, (s_tgt[m] - m_excl[m]) * 0.5f);

        float mx = margin[0];
        #pragma unroll
        for (int m = 1; m < 5; m++) mx = fmaxf(mx, margin[m]);
        float e[5], s = 0.0f;
        #pragma unroll
        for (int m = 0; m < 5; m++) { e[m] = __expf(margin[m] - mx); s += e[m]; }
        float inv = 1.0f / s;
        float* dst = out_thr + (size_t)row * 5;
        #pragma unroll
        for (int m = 0; m < 5; m++) dst[m] = e[m] * inv;

        // ---- global max: atomic accumulate, last block publishes + resets ----
        atomicMax(&g_gmax, fmap(g));
        __threadfence();
        unsigned c = atomicAdd(&g_count, 1);
        if (c == gridDim.x - 1) {
            unsigned final_u = atomicMax(&g_gmax, 0u);
            *out_max = funmap(final_u);
            atomicExch(&g_gmax, 0u);
            atomicExch(&g_count, 0u);
        }
    }
}

extern "C" void kernel_launch(void* const* d_in, const int* in_sizes, int n_in,
                              void* d_out, int out_size)
{
    const float* o1  = (const float*)d_in[0];
    const float* o2  = (const float*)d_in[1];
    const float* o3  = (const float*)d_in[2];
    const float* o4  = (const float*)d_in[3];
    const float* mim = (const float*)d_in[4];
    const int*   tgt = (const int*)d_in[5];

    const int n = in_sizes[5];          // 16384 rows
    float* out = (float*)d_out;

    float* out_thr = out + ((size_t)out_size - (size_t)n * 5);
    float* out_max = out;

    margin_kernel<<<n, 128>>>(o1, o2, o3, o4, mim, tgt, out_max, out_thr);
}